// round 9
// baseline (speedup 1.0000x reference)
#include <cuda_runtime.h>
#include <cuda_fp16.h>
#include <cstdint>

// Problem constants
#define B_   4
#define C_   256
#define H_   160
#define W_   160
#define HW_  (H_ * W_)          // 25600
#define N_   512
#define PH_  8
#define PW_  64

// 50 MB scratch: features transposed to (B, H*W, C) in fp16 so channel reads
// coalesce AND the whole table stays resident in the 126 MB L2.
__device__ __half g_featT[(size_t)B_ * HW_ * C_];

// ---------------------------------------------------------------------------
// Kernel 1: (B, C, H*W) fp32 -> (B, H*W, C) fp16 tiled transpose.
// 64-channel x 32-spatial tiles so fp16 writes are full 128B wavefronts.
// grid (HW/32=800, C/64=4, B=4), block (32, 8)
// ---------------------------------------------------------------------------
__global__ void __launch_bounds__(256) transpose_kernel(const float* __restrict__ in)
{
    __shared__ float tile[64][33];

    const int b     = blockIdx.z;
    const int cBase = blockIdx.y * 64;
    const int sBase = blockIdx.x * 32;
    const int tx = threadIdx.x;
    const int ty = threadIdx.y;

    const float* src = in + (size_t)b * C_ * HW_;
#pragma unroll
    for (int j = 0; j < 64; j += 8)
        tile[ty + j][tx] = __ldcs(&src[(size_t)(cBase + ty + j) * HW_ + sBase + tx]);

    __syncthreads();

    __half2* dst2 = (__half2*)(g_featT + (size_t)b * HW_ * C_);
#pragma unroll
    for (int m = 0; m < 4; ++m) {
        const int s = ty + 8 * m;
        const float lo = tile[2 * tx][s];
        const float hi = tile[2 * tx + 1][s];
        dst2[((size_t)(sBase + s) * C_ + cBase) / 2 + tx] = __floats2half2_rn(lo, hi);
    }
}

// ---------------------------------------------------------------------------
// Kernel 2: rotated ROI align on channel-last fp16 features.
// One block per (n, py): grid = N*PH = 4096 blocks, 256 threads.
// Phase 1: 4 iterations x px-PAIR per warp, 8 independent LDG.128 per
//          iteration. __launch_bounds__(256,4) gives a 64-reg budget so all
//          8 loads stay in flight (real MLP, unlike the 48-reg version).
// Phase 2: px-QUAD per thread: 4 conflict-free LDS.128 -> 8 coalesced
//          streaming STG.128 (4 px x fp32 each).
// Swizzle rotation keyed on (px>>2): conflict-free in both phases.
// ---------------------------------------------------------------------------
__global__ void __launch_bounds__(256, 4) rroi_kernel(const float* __restrict__ rois,
                                                      float* __restrict__ out)
{
    __shared__ uint4  tile[PW_ * 32];       // 64 px x 32 groups x 8 fp16 ch = 32 KB
    __shared__ float4 s_w4[PW_];            // bilinear weights per px
    __shared__ int4   s_off4[PW_];          // corner base offsets (uint4 = 8-half units)

    const int bid = blockIdx.x;
    const int n   = bid >> 3;
    const int py  = bid & 7;
    const int t   = threadIdx.x;

    // ---- per-px sample precompute (threads 0..63) ----
    if (t < PW_) {
        const float* r = rois + n * 6;
        const int   b  = (int)r[0];
        const float cx = r[1];
        const float cy = r[2];
        const float rh = r[3];
        const float rw = r[4];
        const float th = r[5];

        const float sx = rw * (1.0f / PW_);
        const float sy = rh * (1.0f / PH_);
        const float ct = cosf(th);
        const float st = sinf(th);

        const float yy = ((float)py + 0.5f - PH_ * 0.5f) * sy;
        const float xx = ((float)t  + 0.5f - PW_ * 0.5f) * sx;

        const float x = ct * xx + st * yy + cx;
        const float y = -st * xx + ct * yy + cy;

        const float x0f = floorf(x);
        const float y0f = floorf(y);
        const float lx = x - x0f;
        const float ly = y - y0f;
        const int x0 = (int)x0f;
        const int y0 = (int)y0f;
        const int x1 = x0 + 1;
        const int y1 = y0 + 1;

        const bool vx0 = (x0 >= 0) && (x0 < W_);
        const bool vx1 = (x1 >= 0) && (x1 < W_);
        const bool vy0 = (y0 >= 0) && (y0 < H_);
        const bool vy1 = (y1 >= 0) && (y1 < H_);

        float4 wv;
        wv.x = (1.0f - lx) * (1.0f - ly) * ((vy0 && vx0) ? 1.0f : 0.0f);
        wv.y = lx          * (1.0f - ly) * ((vy0 && vx1) ? 1.0f : 0.0f);
        wv.z = (1.0f - lx) * ly          * ((vy1 && vx0) ? 1.0f : 0.0f);
        wv.w = lx          * ly          * ((vy1 && vx1) ? 1.0f : 0.0f);

        const int x0c = min(max(x0, 0), W_ - 1);
        const int x1c = min(max(x1, 0), W_ - 1);
        const int y0c = min(max(y0, 0), H_ - 1);
        const int y1c = min(max(y1, 0), H_ - 1);

        const int base = b * HW_;
        int4 ov;   // offsets in uint4 units (8 halfs): pos * C_/8 = pos * 32
        ov.x = (base + y0c * W_ + x0c) * (C_ / 8);
        ov.y = (base + y0c * W_ + x1c) * (C_ / 8);
        ov.z = (base + y1c * W_ + x0c) * (C_ / 8);
        ov.w = (base + y1c * W_ + x1c) * (C_ / 8);

        s_w4[t]   = wv;
        s_off4[t] = ov;
    }
    __syncthreads();

    const int warp = t >> 5;
    const int lane = t & 31;
    const uint4* featU = (const uint4*)g_featT;   // one uint4 = 8 fp16 channels

    // ---- phase 1: gather + bilinear, px pairs for doubled MLP ----
#pragma unroll
    for (int i = 0; i < 4; ++i) {
        const int px0 = warp * 8 + 2 * i;
        const int px1 = px0 + 1;
        const int rot = px0 >> 2;           // quad-keyed rotation
        const int col = (lane + rot) & 31;

        const float4 wA = s_w4[px0];
        const float4 wB = s_w4[px1];
        const int4   oA = s_off4[px0];
        const int4   oB = s_off4[px1];

        // 8 independent 128-bit gathers (all live with the 64-reg budget)
        const uint4 a00 = __ldg(featU + oA.x + lane);
        const uint4 a01 = __ldg(featU + oA.y + lane);
        const uint4 a10 = __ldg(featU + oA.z + lane);
        const uint4 a11 = __ldg(featU + oA.w + lane);
        const uint4 b00 = __ldg(featU + oB.x + lane);
        const uint4 b01 = __ldg(featU + oB.y + lane);
        const uint4 b10 = __ldg(featU + oB.z + lane);
        const uint4 b11 = __ldg(featU + oB.w + lane);

        uint4 packedA, packedB;
#pragma unroll
        for (int q = 0; q < 4; ++q) {
            const float2 pa = __half22float2(((const __half2*)&a00)[q]);
            const float2 pb = __half22float2(((const __half2*)&a01)[q]);
            const float2 pc = __half22float2(((const __half2*)&a10)[q]);
            const float2 pd = __half22float2(((const __half2*)&a11)[q]);
            const float ax = wA.x * pa.x + wA.y * pb.x + wA.z * pc.x + wA.w * pd.x;
            const float ay = wA.x * pa.y + wA.y * pb.y + wA.z * pc.y + wA.w * pd.y;
            ((__half2*)&packedA)[q] = __floats2half2_rn(ax, ay);
        }
#pragma unroll
        for (int q = 0; q < 4; ++q) {
            const float2 pa = __half22float2(((const __half2*)&b00)[q]);
            const float2 pb = __half22float2(((const __half2*)&b01)[q]);
            const float2 pc = __half22float2(((const __half2*)&b10)[q]);
            const float2 pd = __half22float2(((const __half2*)&b11)[q]);
            const float bx = wB.x * pa.x + wB.y * pb.x + wB.z * pc.x + wB.w * pd.x;
            const float by = wB.x * pa.y + wB.y * pb.y + wB.z * pc.y + wB.w * pd.y;
            ((__half2*)&packedB)[q] = __floats2half2_rn(bx, by);
        }

        tile[px0 * 32 + col] = packedA;
        tile[px1 * 32 + col] = packedB;
    }
    __syncthreads();

    // ---- phase 2: px quads, conflict-free LDS.128, coalesced STG.128 ----
    const unsigned out_base = (unsigned)n * (C_ * PH_ * PW_) + (unsigned)py * PW_;
    const int q_  = t & 15;      // px quad index: px {4q..4q+3}
    const int gb  = t >> 4;      // 0..15 -> channel groups {2gb, 2gb+1}
#pragma unroll
    for (int k = 0; k < 2; ++k) {
        const int g   = gb * 2 + k;                  // 0..31
        const int col = (g + q_) & 31;               // rotation = px>>2 = q_
        const uint4 v0 = tile[(4 * q_)     * 32 + col];
        const uint4 v1 = tile[(4 * q_ + 1) * 32 + col];
        const uint4 v2 = tile[(4 * q_ + 2) * 32 + col];
        const uint4 v3 = tile[(4 * q_ + 3) * 32 + col];
        const int cbase = g * 8;
        const unsigned o0 = out_base + (unsigned)cbase * (PH_ * PW_) + 4 * q_;
#pragma unroll
        for (int qq = 0; qq < 4; ++qq) {
            const float2 f0 = __half22float2(((const __half2*)&v0)[qq]);
            const float2 f1 = __half22float2(((const __half2*)&v1)[qq]);
            const float2 f2 = __half22float2(((const __half2*)&v2)[qq]);
            const float2 f3 = __half22float2(((const __half2*)&v3)[qq]);
            const float4 sA = make_float4(f0.x, f1.x, f2.x, f3.x);  // ch cbase+2qq
            const float4 sB = make_float4(f0.y, f1.y, f2.y, f3.y);  // ch cbase+2qq+1
            __stcs((float4*)(out + o0 + (2 * qq)     * (PH_ * PW_)), sA);
            __stcs((float4*)(out + o0 + (2 * qq + 1) * (PH_ * PW_)), sB);
        }
    }
}

// ---------------------------------------------------------------------------
extern "C" void kernel_launch(void* const* d_in, const int* in_sizes, int n_in,
                              void* d_out, int out_size)
{
    const float* features = (const float*)d_in[0];
    const float* rois     = (const float*)d_in[1];
    float* out            = (float*)d_out;

    dim3 tgrid(HW_ / 32, C_ / 64, B_);
    dim3 tblk(32, 8);
    transpose_kernel<<<tgrid, tblk>>>(features);

    rroi_kernel<<<N_ * PH_, 256>>>(rois, out);
}

// round 10
// speedup vs baseline: 1.0183x; 1.0183x over previous
#include <cuda_runtime.h>
#include <cuda_fp16.h>
#include <cstdint>

// Problem constants
#define B_   4
#define C_   256
#define H_   160
#define W_   160
#define HW_  (H_ * W_)          // 25600
#define N_   512
#define PH_  8
#define PW_  64

// 50 MB scratch: features transposed to (B, H*W, C) in fp16 so channel reads
// coalesce AND the whole table stays resident in the 126 MB L2.
__device__ __half g_featT[(size_t)B_ * HW_ * C_];

// ---------------------------------------------------------------------------
// Kernel 1: (B, C, H*W) fp32 -> (B, H*W, C) fp16 tiled transpose.
// 64-channel x 32-spatial tiles so fp16 writes are full 128B wavefronts.
// grid (HW/32=800, C/64=4, B=4), block (32, 8)
// ---------------------------------------------------------------------------
__global__ void __launch_bounds__(256) transpose_kernel(const float* __restrict__ in)
{
    __shared__ float tile[64][33];

    const int b     = blockIdx.z;
    const int cBase = blockIdx.y * 64;
    const int sBase = blockIdx.x * 32;
    const int tx = threadIdx.x;
    const int ty = threadIdx.y;

    const float* src = in + (size_t)b * C_ * HW_;
#pragma unroll
    for (int j = 0; j < 64; j += 8)
        tile[ty + j][tx] = __ldcs(&src[(size_t)(cBase + ty + j) * HW_ + sBase + tx]);

    __syncthreads();

    __half2* dst2 = (__half2*)(g_featT + (size_t)b * HW_ * C_);
#pragma unroll
    for (int m = 0; m < 4; ++m) {
        const int s = ty + 8 * m;
        const float lo = tile[2 * tx][s];
        const float hi = tile[2 * tx + 1][s];
        dst2[((size_t)(sBase + s) * C_ + cBase) / 2 + tx] = __floats2half2_rn(lo, hi);
    }
}

// ---------------------------------------------------------------------------
// Kernel 2: rotated ROI align on channel-last fp16 features.
// One block per (n, py): grid = N*PH = 4096 blocks, 256 threads.
// The block is split into two INDEPENDENT 128-thread halves; half h owns
// px [32h, 32h+32) and its own disjoint tile rows, synchronized with a
// named barrier (bar.sync h+1, 128). The halves drift out of phase so one
// half's gather burst overlaps the other's store burst (steadier L1 use,
// half the barrier skew).
// Phase 1 (per half): 4 iterations x px-PAIR per warp -> 8 independent
//   LDG.128 in flight. fp32 math, fp16 rotation-swizzled tile (rot = px>>1).
// Phase 2 (per half): lanes = px pairs; conflict-free LDS.128, coalesced
//   streaming STG.64 (two 128B segments per warp store).
// ---------------------------------------------------------------------------
__global__ void __launch_bounds__(256, 5) rroi_kernel(const float* __restrict__ rois,
                                                      float* __restrict__ out)
{
    __shared__ uint4  tile[PW_ * 32];       // 64 px x 32 groups x 8 fp16 ch = 32 KB
    __shared__ float4 s_w4[PW_];            // bilinear weights per px
    __shared__ int4   s_off4[PW_];          // corner base offsets (uint4 = 8-half units)

    const int bid = blockIdx.x;
    const int n   = bid >> 3;
    const int py  = bid & 7;
    const int t   = threadIdx.x;

    const int h   = t >> 7;                 // half 0/1
    const int lt  = t & 127;                // thread within half

    // ---- per-px sample precompute: threads 0..31 of each half do its 32 px ----
    if (lt < 32) {
        const int px = h * 32 + lt;

        const float* r = rois + n * 6;
        const int   b  = (int)r[0];
        const float cx = r[1];
        const float cy = r[2];
        const float rh = r[3];
        const float rw = r[4];
        const float th = r[5];

        const float sx = rw * (1.0f / PW_);
        const float sy = rh * (1.0f / PH_);
        const float ct = cosf(th);
        const float st = sinf(th);

        const float yy = ((float)py + 0.5f - PH_ * 0.5f) * sy;
        const float xx = ((float)px + 0.5f - PW_ * 0.5f) * sx;

        const float x = ct * xx + st * yy + cx;
        const float y = -st * xx + ct * yy + cy;

        const float x0f = floorf(x);
        const float y0f = floorf(y);
        const float lx = x - x0f;
        const float ly = y - y0f;
        const int x0 = (int)x0f;
        const int y0 = (int)y0f;
        const int x1 = x0 + 1;
        const int y1 = y0 + 1;

        const bool vx0 = (x0 >= 0) && (x0 < W_);
        const bool vx1 = (x1 >= 0) && (x1 < W_);
        const bool vy0 = (y0 >= 0) && (y0 < H_);
        const bool vy1 = (y1 >= 0) && (y1 < H_);

        float4 wv;
        wv.x = (1.0f - lx) * (1.0f - ly) * ((vy0 && vx0) ? 1.0f : 0.0f);
        wv.y = lx          * (1.0f - ly) * ((vy0 && vx1) ? 1.0f : 0.0f);
        wv.z = (1.0f - lx) * ly          * ((vy1 && vx0) ? 1.0f : 0.0f);
        wv.w = lx          * ly          * ((vy1 && vx1) ? 1.0f : 0.0f);

        const int x0c = min(max(x0, 0), W_ - 1);
        const int x1c = min(max(x1, 0), W_ - 1);
        const int y0c = min(max(y0, 0), H_ - 1);
        const int y1c = min(max(y1, 0), H_ - 1);

        const int base = b * HW_;
        int4 ov;   // offsets in uint4 units (8 halfs): pos * C_/8 = pos * 32
        ov.x = (base + y0c * W_ + x0c) * (C_ / 8);
        ov.y = (base + y0c * W_ + x1c) * (C_ / 8);
        ov.z = (base + y1c * W_ + x0c) * (C_ / 8);
        ov.w = (base + y1c * W_ + x1c) * (C_ / 8);

        s_w4[px]   = wv;
        s_off4[px] = ov;
    }
    // half-local barrier (ids 1 and 2)
    asm volatile("bar.sync %0, %1;" :: "r"(h + 1), "r"(128) : "memory");

    const int wl   = (t >> 5) & 3;          // warp within half, 0..3
    const int lane = t & 31;
    const uint4* featU = (const uint4*)g_featT;   // one uint4 = 8 fp16 channels

    // ---- phase 1: gather + bilinear, px pairs for doubled MLP ----
#pragma unroll
    for (int i = 0; i < 4; ++i) {
        const int px0 = h * 32 + wl * 8 + 2 * i;
        const int px1 = px0 + 1;
        const int rot = px0 >> 1;           // shared rotation for the pair
        const int col = (lane + rot) & 31;

        const float4 wA = s_w4[px0];
        const float4 wB = s_w4[px1];
        const int4   oA = s_off4[px0];
        const int4   oB = s_off4[px1];

        // 8 independent 128-bit gathers
        const uint4 a00 = __ldg(featU + oA.x + lane);
        const uint4 a01 = __ldg(featU + oA.y + lane);
        const uint4 a10 = __ldg(featU + oA.z + lane);
        const uint4 a11 = __ldg(featU + oA.w + lane);
        const uint4 b00 = __ldg(featU + oB.x + lane);
        const uint4 b01 = __ldg(featU + oB.y + lane);
        const uint4 b10 = __ldg(featU + oB.z + lane);
        const uint4 b11 = __ldg(featU + oB.w + lane);

        uint4 packedA, packedB;
#pragma unroll
        for (int q = 0; q < 4; ++q) {
            const float2 pa = __half22float2(((const __half2*)&a00)[q]);
            const float2 pb = __half22float2(((const __half2*)&a01)[q]);
            const float2 pc = __half22float2(((const __half2*)&a10)[q]);
            const float2 pd = __half22float2(((const __half2*)&a11)[q]);
            const float ax = wA.x * pa.x + wA.y * pb.x + wA.z * pc.x + wA.w * pd.x;
            const float ay = wA.x * pa.y + wA.y * pb.y + wA.z * pc.y + wA.w * pd.y;
            ((__half2*)&packedA)[q] = __floats2half2_rn(ax, ay);
        }
#pragma unroll
        for (int q = 0; q < 4; ++q) {
            const float2 pa = __half22float2(((const __half2*)&b00)[q]);
            const float2 pb = __half22float2(((const __half2*)&b01)[q]);
            const float2 pc = __half22float2(((const __half2*)&b10)[q]);
            const float2 pd = __half22float2(((const __half2*)&b11)[q]);
            const float bx = wB.x * pa.x + wB.y * pb.x + wB.z * pc.x + wB.w * pd.x;
            const float by = wB.x * pa.y + wB.y * pb.y + wB.z * pc.y + wB.w * pd.y;
            ((__half2*)&packedB)[q] = __floats2half2_rn(bx, by);
        }

        tile[px0 * 32 + col] = packedA;
        tile[px1 * 32 + col] = packedB;
    }
    asm volatile("bar.sync %0, %1;" :: "r"(h + 1), "r"(128) : "memory");

    // ---- phase 2: lanes = px pairs (within half), coalesced streaming STG.64 ----
    const unsigned out_base = (unsigned)n * (C_ * PH_ * PW_) + (unsigned)py * PW_;
    const int pp_l = lt & 15;               // local pair index 0..15
    const int gb   = lt >> 4;               // 0..7
    const int pp   = h * 16 + pp_l;         // global pair: px {2pp, 2pp+1}
#pragma unroll
    for (int k = 0; k < 4; ++k) {
        const int g   = gb * 4 + k;                  // 0..31
        const int col = (g + pp) & 31;               // rotation = px>>1 = pp
        const uint4 v0 = tile[(2 * pp)     * 32 + col];
        const uint4 v1 = tile[(2 * pp + 1) * 32 + col];
        const int cbase = g * 8;
        const unsigned o0 = out_base + (unsigned)cbase * (PH_ * PW_) + 2 * pp;
#pragma unroll
        for (int q = 0; q < 4; ++q) {
            const float2 f0 = __half22float2(((const __half2*)&v0)[q]);
            const float2 f1 = __half22float2(((const __half2*)&v1)[q]);
            const float2 sA = make_float2(f0.x, f1.x);
            const float2 sB = make_float2(f0.y, f1.y);
            __stcs((float2*)(out + o0 + (2 * q)     * (PH_ * PW_)), sA);
            __stcs((float2*)(out + o0 + (2 * q + 1) * (PH_ * PW_)), sB);
        }
    }
}

// ---------------------------------------------------------------------------
extern "C" void kernel_launch(void* const* d_in, const int* in_sizes, int n_in,
                              void* d_out, int out_size)
{
    const float* features = (const float*)d_in[0];
    const float* rois     = (const float*)d_in[1];
    float* out            = (float*)d_out;

    dim3 tgrid(HW_ / 32, C_ / 64, B_);
    dim3 tblk(32, 8);
    transpose_kernel<<<tgrid, tblk>>>(features);

    rroi_kernel<<<N_ * PH_, 256>>>(rois, out);
}

// round 12
// speedup vs baseline: 1.0524x; 1.0335x over previous
#include <cuda_runtime.h>
#include <cuda_fp16.h>
#include <cstdint>

// Problem constants
#define B_   4
#define C_   256
#define H_   160
#define W_   160
#define HW_  (H_ * W_)          // 25600
#define N_   512
#define PH_  8
#define PW_  64

// 50 MB scratch: features transposed to (B, H*W, C) in fp16 so channel reads
// coalesce AND the whole table stays resident in the 126 MB L2.
__device__ __half g_featT[(size_t)B_ * HW_ * C_];

// ---------------------------------------------------------------------------
// Kernel 1: (B, C, H*W) fp32 -> (B, H*W, C) fp16 tiled transpose.
// 64-channel x 32-spatial tiles so fp16 writes are full 128B wavefronts.
// grid (HW/32=800, C/64=4, B=4), block (32, 8)
// ---------------------------------------------------------------------------
__global__ void __launch_bounds__(256) transpose_kernel(const float* __restrict__ in)
{
    __shared__ float tile[64][33];

    const int b     = blockIdx.z;
    const int cBase = blockIdx.y * 64;
    const int sBase = blockIdx.x * 32;
    const int tx = threadIdx.x;
    const int ty = threadIdx.y;

    const float* src = in + (size_t)b * C_ * HW_;
#pragma unroll
    for (int j = 0; j < 64; j += 8)
        tile[ty + j][tx] = __ldcs(&src[(size_t)(cBase + ty + j) * HW_ + sBase + tx]);

    __syncthreads();

    __half2* dst2 = (__half2*)(g_featT + (size_t)b * HW_ * C_);
#pragma unroll
    for (int m = 0; m < 4; ++m) {
        const int s = ty + 8 * m;
        const float lo = tile[2 * tx][s];
        const float hi = tile[2 * tx + 1][s];
        dst2[((size_t)(sBase + s) * C_ + cBase) / 2 + tx] = __floats2half2_rn(lo, hi);
    }
}

// ---------------------------------------------------------------------------
// Kernel 2: rotated ROI align on channel-last fp16 features.
// 128-thread blocks, 8192 of them: block owns 32 px of one (n, py) row.
// Small blocks -> 10 blocks/SM (40 warps, ~62% occ), fine-grained chip-wide
// phase mixing, small barrier skew.
// Phase 1: 4 warps x 4 px-pair iterations; 8 independent LDG.128 in flight
//          per iteration. fp32 math, fp16 rotation-swizzled tile (rot=px>>2).
// Phase 2: px-QUAD per thread: conflict-free LDS.128 -> coalesced streaming
//          STG.128 (4 px x fp32 per instruction, 4x128B segments per warp).
// ---------------------------------------------------------------------------
__global__ void __launch_bounds__(128, 10) rroi_kernel(const float* __restrict__ rois,
                                                       float* __restrict__ out)
{
    __shared__ uint4  tile[32 * 32];        // 32 px x 32 groups x 8 fp16 ch = 16 KB
    __shared__ float4 s_w4[32];             // bilinear weights per local px
    __shared__ int4   s_off4[32];           // corner base offsets (uint4 units)

    const int bid = blockIdx.x;
    const int n   = bid >> 4;               // 512 rois
    const int py  = (bid >> 1) & 7;         // 8 rows
    const int h   = bid & 1;                // px half: [32h, 32h+32)
    const int t   = threadIdx.x;

    // ---- per-px sample precompute (threads 0..31) ----
    if (t < 32) {
        const int px = h * 32 + t;

        const float* r = rois + n * 6;
        const int   b  = (int)r[0];
        const float cx = r[1];
        const float cy = r[2];
        const float rh = r[3];
        const float rw = r[4];
        const float th = r[5];

        const float sx = rw * (1.0f / PW_);
        const float sy = rh * (1.0f / PH_);
        const float ct = cosf(th);
        const float st = sinf(th);

        const float yy = ((float)py + 0.5f - PH_ * 0.5f) * sy;
        const float xx = ((float)px + 0.5f - PW_ * 0.5f) * sx;

        const float x = ct * xx + st * yy + cx;
        const float y = -st * xx + ct * yy + cy;

        const float x0f = floorf(x);
        const float y0f = floorf(y);
        const float lx = x - x0f;
        const float ly = y - y0f;
        const int x0 = (int)x0f;
        const int y0 = (int)y0f;
        const int x1 = x0 + 1;
        const int y1 = y0 + 1;

        const bool vx0 = (x0 >= 0) && (x0 < W_);
        const bool vx1 = (x1 >= 0) && (x1 < W_);
        const bool vy0 = (y0 >= 0) && (y0 < H_);
        const bool vy1 = (y1 >= 0) && (y1 < H_);

        float4 wv;
        wv.x = (1.0f - lx) * (1.0f - ly) * ((vy0 && vx0) ? 1.0f : 0.0f);
        wv.y = lx          * (1.0f - ly) * ((vy0 && vx1) ? 1.0f : 0.0f);
        wv.z = (1.0f - lx) * ly          * ((vy1 && vx0) ? 1.0f : 0.0f);
        wv.w = lx          * ly          * ((vy1 && vx1) ? 1.0f : 0.0f);

        const int x0c = min(max(x0, 0), W_ - 1);
        const int x1c = min(max(x1, 0), W_ - 1);
        const int y0c = min(max(y0, 0), H_ - 1);
        const int y1c = min(max(y1, 0), H_ - 1);

        const int base = b * HW_;
        int4 ov;   // offsets in uint4 units (8 halfs): pos * C_/8 = pos * 32
        ov.x = (base + y0c * W_ + x0c) * (C_ / 8);
        ov.y = (base + y0c * W_ + x1c) * (C_ / 8);
        ov.z = (base + y1c * W_ + x0c) * (C_ / 8);
        ov.w = (base + y1c * W_ + x1c) * (C_ / 8);

        s_w4[t]   = wv;
        s_off4[t] = ov;
    }
    __syncthreads();

    const int warp = t >> 5;                // 0..3
    const int lane = t & 31;
    const uint4* featU = (const uint4*)g_featT;   // one uint4 = 8 fp16 channels

    // ---- phase 1: gather + bilinear, px pairs for doubled MLP ----
#pragma unroll
    for (int i = 0; i < 4; ++i) {
        const int pxl0 = warp * 8 + 2 * i;  // local px in [0,32)
        const int pxl1 = pxl0 + 1;
        const int rot  = (h * 32 + pxl0) >> 2;   // quad-keyed rotation (global px)
        const int col  = (lane + rot) & 31;

        const float4 wA = s_w4[pxl0];
        const float4 wB = s_w4[pxl1];
        const int4   oA = s_off4[pxl0];
        const int4   oB = s_off4[pxl1];

        // 8 independent 128-bit gathers
        const uint4 a00 = __ldg(featU + oA.x + lane);
        const uint4 a01 = __ldg(featU + oA.y + lane);
        const uint4 a10 = __ldg(featU + oA.z + lane);
        const uint4 a11 = __ldg(featU + oA.w + lane);
        const uint4 b00 = __ldg(featU + oB.x + lane);
        const uint4 b01 = __ldg(featU + oB.y + lane);
        const uint4 b10 = __ldg(featU + oB.z + lane);
        const uint4 b11 = __ldg(featU + oB.w + lane);

        uint4 packedA, packedB;
#pragma unroll
        for (int q = 0; q < 4; ++q) {
            const float2 pa = __half22float2(((const __half2*)&a00)[q]);
            const float2 pb = __half22float2(((const __half2*)&a01)[q]);
            const float2 pc = __half22float2(((const __half2*)&a10)[q]);
            const float2 pd = __half22float2(((const __half2*)&a11)[q]);
            const float ax = wA.x * pa.x + wA.y * pb.x + wA.z * pc.x + wA.w * pd.x;
            const float ay = wA.x * pa.y + wA.y * pb.y + wA.z * pc.y + wA.w * pd.y;
            ((__half2*)&packedA)[q] = __floats2half2_rn(ax, ay);
        }
#pragma unroll
        for (int q = 0; q < 4; ++q) {
            const float2 pa = __half22float2(((const __half2*)&b00)[q]);
            const float2 pb = __half22float2(((const __half2*)&b01)[q]);
            const float2 pc = __half22float2(((const __half2*)&b10)[q]);
            const float2 pd = __half22float2(((const __half2*)&b11)[q]);
            const float bx = wB.x * pa.x + wB.y * pb.x + wB.z * pc.x + wB.w * pd.x;
            const float by = wB.x * pa.y + wB.y * pb.y + wB.z * pc.y + wB.w * pd.y;
            ((__half2*)&packedB)[q] = __floats2half2_rn(bx, by);
        }

        tile[pxl0 * 32 + col] = packedA;
        tile[pxl1 * 32 + col] = packedB;
    }
    __syncthreads();

    // ---- phase 2: px quads, conflict-free LDS.128, coalesced STG.128 ----
    const unsigned out_base = (unsigned)n * (C_ * PH_ * PW_) + (unsigned)py * PW_
                            + (unsigned)h * 32;
    const int q_  = t & 7;       // local px quad: px {4q..4q+3}
    const int gb  = t >> 3;      // 0..15 -> channel groups {2gb, 2gb+1}
    const int rotq = h * 8 + q_; // global quad rotation
#pragma unroll
    for (int k = 0; k < 2; ++k) {
        const int g   = gb * 2 + k;                  // 0..31
        const int col = (g + rotq) & 31;
        const uint4 v0 = tile[(4 * q_)     * 32 + col];
        const uint4 v1 = tile[(4 * q_ + 1) * 32 + col];
        const uint4 v2 = tile[(4 * q_ + 2) * 32 + col];
        const uint4 v3 = tile[(4 * q_ + 3) * 32 + col];
        const int cbase = g * 8;
        const unsigned o0 = out_base + (unsigned)cbase * (PH_ * PW_) + 4 * q_;
#pragma unroll
        for (int qq = 0; qq < 4; ++qq) {
            const float2 f0 = __half22float2(((const __half2*)&v0)[qq]);
            const float2 f1 = __half22float2(((const __half2*)&v1)[qq]);
            const float2 f2 = __half22float2(((const __half2*)&v2)[qq]);
            const float2 f3 = __half22float2(((const __half2*)&v3)[qq]);
            const float4 sA = make_float4(f0.x, f1.x, f2.x, f3.x);  // ch cbase+2qq
            const float4 sB = make_float4(f0.y, f1.y, f2.y, f3.y);  // ch cbase+2qq+1
            __stcs((float4*)(out + o0 + (2 * qq)     * (PH_ * PW_)), sA);
            __stcs((float4*)(out + o0 + (2 * qq + 1) * (PH_ * PW_)), sB);
        }
    }
}

// ---------------------------------------------------------------------------
extern "C" void kernel_launch(void* const* d_in, const int* in_sizes, int n_in,
                              void* d_out, int out_size)
{
    const float* features = (const float*)d_in[0];
    const float* rois     = (const float*)d_in[1];
    float* out            = (float*)d_out;

    dim3 tgrid(HW_ / 32, C_ / 64, B_);
    dim3 tblk(32, 8);
    transpose_kernel<<<tgrid, tblk>>>(features);

    rroi_kernel<<<N_ * PH_ * 2, 128>>>(rois, out);
}

// round 13
// speedup vs baseline: 1.0723x; 1.0189x over previous
#include <cuda_runtime.h>
#include <cuda_fp16.h>
#include <cstdint>

// Problem constants
#define B_   4
#define C_   256
#define H_   160
#define W_   160
#define HW_  (H_ * W_)          // 25600
#define N_   512
#define PH_  8
#define PW_  64

// 50 MB scratch: features transposed to (B, H*W, C) in fp16 so channel reads
// coalesce AND the whole table stays resident in the 126 MB L2.
__device__ __half g_featT[(size_t)B_ * HW_ * C_];

// ---------------------------------------------------------------------------
// Kernel 1: (B, C, H*W) fp32 -> (B, H*W, C) fp16 tiled transpose.
// 64-channel x 32-spatial tiles so fp16 writes are full 128B wavefronts.
// grid (HW/32=800, C/64=4, B=4), block (32, 8)
// ---------------------------------------------------------------------------
__global__ void __launch_bounds__(256) transpose_kernel(const float* __restrict__ in)
{
    __shared__ float tile[64][33];

    const int b     = blockIdx.z;
    const int cBase = blockIdx.y * 64;
    const int sBase = blockIdx.x * 32;
    const int tx = threadIdx.x;
    const int ty = threadIdx.y;

    const float* src = in + (size_t)b * C_ * HW_;
#pragma unroll
    for (int j = 0; j < 64; j += 8)
        tile[ty + j][tx] = __ldcs(&src[(size_t)(cBase + ty + j) * HW_ + sBase + tx]);

    __syncthreads();

    __half2* dst2 = (__half2*)(g_featT + (size_t)b * HW_ * C_);
#pragma unroll
    for (int m = 0; m < 4; ++m) {
        const int s = ty + 8 * m;
        const float lo = tile[2 * tx][s];
        const float hi = tile[2 * tx + 1][s];
        dst2[((size_t)(sBase + s) * C_ + cBase) / 2 + tx] = __floats2half2_rn(lo, hi);
    }
}

// ---------------------------------------------------------------------------
// Kernel 2: rotated ROI align on channel-last fp16 features.
// 128-thread blocks, 8192 of them: block owns 32 px of one (n, py) row.
// Phase 1: 4 warps x 4 px-pair iterations; 8 independent LDG.128 in flight.
//          Interpolation in HALF2 (HFMA2 chains): 16 math insts per px per
//          lane instead of ~52 (no F2F converts, no packs) -> LSU stays fed.
// Phase 2: px-QUAD per thread: conflict-free LDS.128 -> coalesced streaming
//          STG.128 (fp32 output conversion happens here).
// Swizzle rotation keyed on global px>>2: conflict-free in both phases.
// ---------------------------------------------------------------------------
__global__ void __launch_bounds__(128, 10) rroi_kernel(const float* __restrict__ rois,
                                                       float* __restrict__ out)
{
    __shared__ uint4  tile[32 * 32];        // 32 px x 32 groups x 8 fp16 ch = 16 KB
    __shared__ uint4  s_wh[32];             // 4x half2-broadcast weights per local px
    __shared__ int4   s_off4[32];           // corner base offsets (uint4 units)

    const int bid = blockIdx.x;
    const int n   = bid >> 4;               // 512 rois
    const int py  = (bid >> 1) & 7;         // 8 rows
    const int h   = bid & 1;                // px half: [32h, 32h+32)
    const int t   = threadIdx.x;

    // ---- per-px sample precompute (threads 0..31) ----
    if (t < 32) {
        const int px = h * 32 + t;

        const float* r = rois + n * 6;
        const int   b  = (int)r[0];
        const float cx = r[1];
        const float cy = r[2];
        const float rh = r[3];
        const float rw = r[4];
        const float th = r[5];

        const float sx = rw * (1.0f / PW_);
        const float sy = rh * (1.0f / PH_);
        const float ct = cosf(th);
        const float st = sinf(th);

        const float yy = ((float)py + 0.5f - PH_ * 0.5f) * sy;
        const float xx = ((float)px + 0.5f - PW_ * 0.5f) * sx;

        const float x = ct * xx + st * yy + cx;
        const float y = -st * xx + ct * yy + cy;

        const float x0f = floorf(x);
        const float y0f = floorf(y);
        const float lx = x - x0f;
        const float ly = y - y0f;
        const int x0 = (int)x0f;
        const int y0 = (int)y0f;
        const int x1 = x0 + 1;
        const int y1 = y0 + 1;

        const bool vx0 = (x0 >= 0) && (x0 < W_);
        const bool vx1 = (x1 >= 0) && (x1 < W_);
        const bool vy0 = (y0 >= 0) && (y0 < H_);
        const bool vy1 = (y1 >= 0) && (y1 < H_);

        const float w00 = (1.0f - lx) * (1.0f - ly) * ((vy0 && vx0) ? 1.0f : 0.0f);
        const float w01 = lx          * (1.0f - ly) * ((vy0 && vx1) ? 1.0f : 0.0f);
        const float w10 = (1.0f - lx) * ly          * ((vy1 && vx0) ? 1.0f : 0.0f);
        const float w11 = lx          * ly          * ((vy1 && vx1) ? 1.0f : 0.0f);

        // broadcast weights to half2 once per px
        uint4 wh;
        ((__half2*)&wh)[0] = __half2half2(__float2half_rn(w00));
        ((__half2*)&wh)[1] = __half2half2(__float2half_rn(w01));
        ((__half2*)&wh)[2] = __half2half2(__float2half_rn(w10));
        ((__half2*)&wh)[3] = __half2half2(__float2half_rn(w11));

        const int x0c = min(max(x0, 0), W_ - 1);
        const int x1c = min(max(x1, 0), W_ - 1);
        const int y0c = min(max(y0, 0), H_ - 1);
        const int y1c = min(max(y1, 0), H_ - 1);

        const int base = b * HW_;
        int4 ov;   // offsets in uint4 units (8 halfs): pos * C_/8 = pos * 32
        ov.x = (base + y0c * W_ + x0c) * (C_ / 8);
        ov.y = (base + y0c * W_ + x1c) * (C_ / 8);
        ov.z = (base + y1c * W_ + x0c) * (C_ / 8);
        ov.w = (base + y1c * W_ + x1c) * (C_ / 8);

        s_wh[t]   = wh;
        s_off4[t] = ov;
    }
    __syncthreads();

    const int warp = t >> 5;                // 0..3
    const int lane = t & 31;
    const uint4* featU = (const uint4*)g_featT;   // one uint4 = 8 fp16 channels

    // ---- phase 1: gather + half2 bilinear, px pairs for doubled MLP ----
#pragma unroll
    for (int i = 0; i < 4; ++i) {
        const int pxl0 = warp * 8 + 2 * i;  // local px in [0,32)
        const int pxl1 = pxl0 + 1;
        const int rot  = (h * 32 + pxl0) >> 2;   // quad-keyed rotation (global px)
        const int col  = (lane + rot) & 31;

        const uint4 wA = s_wh[pxl0];
        const uint4 wB = s_wh[pxl1];
        const int4  oA = s_off4[pxl0];
        const int4  oB = s_off4[pxl1];

        // 8 independent 128-bit gathers
        const uint4 a00 = __ldg(featU + oA.x + lane);
        const uint4 a01 = __ldg(featU + oA.y + lane);
        const uint4 a10 = __ldg(featU + oA.z + lane);
        const uint4 a11 = __ldg(featU + oA.w + lane);
        const uint4 b00 = __ldg(featU + oB.x + lane);
        const uint4 b01 = __ldg(featU + oB.y + lane);
        const uint4 b10 = __ldg(featU + oB.z + lane);
        const uint4 b11 = __ldg(featU + oB.w + lane);

        const __half2 wA0 = ((const __half2*)&wA)[0];
        const __half2 wA1 = ((const __half2*)&wA)[1];
        const __half2 wA2 = ((const __half2*)&wA)[2];
        const __half2 wA3 = ((const __half2*)&wA)[3];
        const __half2 wB0 = ((const __half2*)&wB)[0];
        const __half2 wB1 = ((const __half2*)&wB)[1];
        const __half2 wB2 = ((const __half2*)&wB)[2];
        const __half2 wB3 = ((const __half2*)&wB)[3];

        uint4 packedA, packedB;
#pragma unroll
        for (int q = 0; q < 4; ++q) {
            __half2 acc = __hmul2(wA0, ((const __half2*)&a00)[q]);
            acc = __hfma2(wA1, ((const __half2*)&a01)[q], acc);
            acc = __hfma2(wA2, ((const __half2*)&a10)[q], acc);
            acc = __hfma2(wA3, ((const __half2*)&a11)[q], acc);
            ((__half2*)&packedA)[q] = acc;
        }
#pragma unroll
        for (int q = 0; q < 4; ++q) {
            __half2 acc = __hmul2(wB0, ((const __half2*)&b00)[q]);
            acc = __hfma2(wB1, ((const __half2*)&b01)[q], acc);
            acc = __hfma2(wB2, ((const __half2*)&b10)[q], acc);
            acc = __hfma2(wB3, ((const __half2*)&b11)[q], acc);
            ((__half2*)&packedB)[q] = acc;
        }

        tile[pxl0 * 32 + col] = packedA;
        tile[pxl1 * 32 + col] = packedB;
    }
    __syncthreads();

    // ---- phase 2: px quads, conflict-free LDS.128, coalesced STG.128 ----
    const unsigned out_base = (unsigned)n * (C_ * PH_ * PW_) + (unsigned)py * PW_
                            + (unsigned)h * 32;
    const int q_  = t & 7;       // local px quad: px {4q..4q+3}
    const int gb  = t >> 3;      // 0..15 -> channel groups {2gb, 2gb+1}
    const int rotq = h * 8 + q_; // global quad rotation
#pragma unroll
    for (int k = 0; k < 2; ++k) {
        const int g   = gb * 2 + k;                  // 0..31
        const int col = (g + rotq) & 31;
        const uint4 v0 = tile[(4 * q_)     * 32 + col];
        const uint4 v1 = tile[(4 * q_ + 1) * 32 + col];
        const uint4 v2 = tile[(4 * q_ + 2) * 32 + col];
        const uint4 v3 = tile[(4 * q_ + 3) * 32 + col];
        const int cbase = g * 8;
        const unsigned o0 = out_base + (unsigned)cbase * (PH_ * PW_) + 4 * q_;
#pragma unroll
        for (int qq = 0; qq < 4; ++qq) {
            const float2 f0 = __half22float2(((const __half2*)&v0)[qq]);
            const float2 f1 = __half22float2(((const __half2*)&v1)[qq]);
            const float2 f2 = __half22float2(((const __half2*)&v2)[qq]);
            const float2 f3 = __half22float2(((const __half2*)&v3)[qq]);
            const float4 sA = make_float4(f0.x, f1.x, f2.x, f3.x);  // ch cbase+2qq
            const float4 sB = make_float4(f0.y, f1.y, f2.y, f3.y);  // ch cbase+2qq+1
            __stcs((float4*)(out + o0 + (2 * qq)     * (PH_ * PW_)), sA);
            __stcs((float4*)(out + o0 + (2 * qq + 1) * (PH_ * PW_)), sB);
        }
    }
}

// ---------------------------------------------------------------------------
extern "C" void kernel_launch(void* const* d_in, const int* in_sizes, int n_in,
                              void* d_out, int out_size)
{
    const float* features = (const float*)d_in[0];
    const float* rois     = (const float*)d_in[1];
    float* out            = (float*)d_out;

    dim3 tgrid(HW_ / 32, C_ / 64, B_);
    dim3 tblk(32, 8);
    transpose_kernel<<<tgrid, tblk>>>(features);

    rroi_kernel<<<N_ * PH_ * 2, 128>>>(rois, out);
}